// round 8
// baseline (speedup 1.0000x reference)
#include <cuda_runtime.h>
#include <cuda_bf16.h>
#include <cstdint>

// Problem constants
#define N_TOK  8192
#define DMODEL 1024
#define NEXP   8
#define HDIM   2816
#define CAP    1280
#define SLOTS  (NEXP * CAP)          // 10240

// ---------------- device scratch (~200 MB total; statics must stay small) --
__device__ int g_slot_of_token[N_TOK];
__device__ int g_token_of_slot[SLOTS];
__device__ int g_count[NEXP];
__device__ __align__(256) __nv_bfloat16 g_xh [(size_t)SLOTS * DMODEL];
__device__ __align__(256) __nv_bfloat16 g_xl [(size_t)SLOTS * DMODEL];
__device__ __align__(256) __nv_bfloat16 g_acth[(size_t)SLOTS * HDIM];
__device__ __align__(256) __nv_bfloat16 g_actl[(size_t)SLOTS * HDIM];
__device__ __align__(256) float g_Y[(size_t)SLOTS * DMODEL];

#define MMA16816(d, a, b0, b1) \
    asm volatile("mma.sync.aligned.m16n8k16.row.col.f32.bf16.bf16.f32 " \
                 "{%0,%1,%2,%3}, {%4,%5,%6,%7}, {%8,%9}, {%0,%1,%2,%3};" \
                 : "+f"((d)[0]), "+f"((d)[1]), "+f"((d)[2]), "+f"((d)[3]) \
                 : "r"((a)[0]), "r"((a)[1]), "r"((a)[2]), "r"((a)[3]), \
                   "r"(b0), "r"(b1))

// split two fp32 into packed bf16x2 hi and lo (lo = residual)
__device__ __forceinline__ void split2(float f0, float f1,
                                       uint32_t& hi, uint32_t& lo) {
    __nv_bfloat16 h0 = __float2bfloat16_rn(f0);
    __nv_bfloat16 h1 = __float2bfloat16_rn(f1);
    __nv_bfloat16 l0 = __float2bfloat16_rn(f0 - __bfloat162float(h0));
    __nv_bfloat16 l1 = __float2bfloat16_rn(f1 - __bfloat162float(h1));
    __nv_bfloat162 hp = __halves2bfloat162(h0, h1);
    __nv_bfloat162 lp = __halves2bfloat162(l0, l1);
    hi = *(uint32_t*)&hp; lo = *(uint32_t*)&lp;
}
__device__ __forceinline__ void split1(float f, __nv_bfloat16& h, __nv_bfloat16& l) {
    h = __float2bfloat16_rn(f);
    l = __float2bfloat16_rn(f - __bfloat162float(h));
}

// ---------------- routing (dtype-adaptive int32/int64) ----------------------
__global__ void route_kernel(const int* __restrict__ idxw) {
    __shared__ int s_any;
    int tid = threadIdx.x;
    if (tid == 0) s_any = 0;
    for (int s = tid; s < SLOTS; s += 256) g_token_of_slot[s] = -1;
    __syncthreads();
    int local = 0;
    for (int i = 2 * tid + 1; i < N_TOK; i += 512) local |= idxw[i];
    if (local) atomicOr(&s_any, 1);
    __syncthreads();
    const int stride = s_any ? 1 : 2;
    int warp = tid >> 5, lane = tid & 31;
    if (warp < NEXP) {
        int e = warp, cnt = 0;
        for (int base = 0; base < N_TOK; base += 32) {
            int t = base + lane;
            int ei = idxw[t * stride];
            bool m = (ei == e);
            unsigned mask = __ballot_sync(0xffffffffu, m);
            if (m) {
                int pos = cnt + __popc(mask & ((1u << lane) - 1u));
                if (pos < CAP) {
                    g_slot_of_token[t] = e * CAP + pos;
                    g_token_of_slot[e * CAP + pos] = t;
                } else {
                    g_slot_of_token[t] = SLOTS;
                }
            }
            cnt += __popc(mask);
        }
        if (lane == 0) g_count[e] = (cnt < CAP) ? cnt : CAP;
    }
}

// ---------------- gather tokens into split bf16 slot buffer ----------------
__global__ void gather_kernel(const float* __restrict__ x) {
    int s = blockIdx.x;
    int tok = g_token_of_slot[s];
    int i = threadIdx.x;              // 0..255 -> float4
    float4 v = make_float4(0.f, 0.f, 0.f, 0.f);
    if (tok >= 0) v = *(const float4*)(x + (size_t)tok * DMODEL + i * 4);
    uint32_t h01, l01, h23, l23;
    split2(v.x, v.y, h01, l01);
    split2(v.z, v.w, h23, l23);
    uint2 hv = make_uint2(h01, h23), lv = make_uint2(l01, l23);
    *(uint2*)(g_xh + (size_t)s * DMODEL + i * 4) = hv;
    *(uint2*)(g_xl + (size_t)s * DMODEL + i * 4) = lv;
}

// ---------------- GEMM tiling ------------------------------------------------
// BM=128, BN=64, BK=16; 256 threads = 8 warps (4m x 2n), warp tile 32x32.
// Double-buffered smem (one __syncthreads per chunk), register prefetch.
// B is staged pre-split (bf16 hi/lo) and TRANSPOSED [n][k] so fragment reads
// use the same conflict-free pattern as A. Row pitch 24 bf16 = 48B: fragment
// banks = 12*fr + fc/2 -> all 32 distinct.
#define BM 128
#define BN 64
#define BK 16
#define KP 24   // row pitch in bf16 (48 bytes)

// ---------------- fused gate+up GEMM ----------------------------------------
__global__ void __launch_bounds__(256, 2) gemm_gu_kernel(
        const float* __restrict__ Wg, const float* __restrict__ Wu) {
    __shared__ __align__(16) __nv_bfloat16 sAh[2][BM][KP];
    __shared__ __align__(16) __nv_bfloat16 sAl[2][BM][KP];
    __shared__ __align__(16) __nv_bfloat16 sBgh[2][BN][KP];
    __shared__ __align__(16) __nv_bfloat16 sBgl[2][BN][KP];
    __shared__ __align__(16) __nv_bfloat16 sBuh[2][BN][KP];
    __shared__ __align__(16) __nv_bfloat16 sBul[2][BN][KP];   // 48KB total

    const int e  = blockIdx.z;
    const int m0 = blockIdx.y * BM;
    if (m0 >= g_count[e]) return;
    const int n0 = blockIdx.x * BN;

    const size_t abase = (size_t)(e * CAP + m0) * DMODEL;
    const float* Bg = Wg + (size_t)e * DMODEL * HDIM;
    const float* Bu = Wu + (size_t)e * DMODEL * HDIM;

    const int tid  = threadIdx.x;
    const int lane = tid & 31, warp = tid >> 5;
    const int wm = warp >> 1, wn = warp & 1;
    const int fr = lane >> 2;
    const int fc = (lane & 3) * 2;

    // A loads: uint4 = 8 bf16; 128 rows x 2 chunks = 256 -> 1/thread
    const int ar = tid >> 1, ac = (tid & 1) * 8;
    // B loads: float4; 16 k-rows x 16 n-chunks = 256 -> 1/thread (per matrix)
    const int bk = tid >> 4, bn = (tid & 15) * 4;

    uint4 pah, pal;
    float4 pbg, pbu;
    auto prefetch = [&](int c) {
        const int k0 = c * BK;
        pah = *(const uint4*)(g_xh + abase + (size_t)ar * DMODEL + k0 + ac);
        pal = *(const uint4*)(g_xl + abase + (size_t)ar * DMODEL + k0 + ac);
        pbg = *(const float4*)(Bg + (size_t)(k0 + bk) * HDIM + n0 + bn);
        pbu = *(const float4*)(Bu + (size_t)(k0 + bk) * HDIM + n0 + bn);
    };

    float accG[2][4][4], accU[2][4][4];
#pragma unroll
    for (int i = 0; i < 2; i++)
#pragma unroll
        for (int j = 0; j < 4; j++)
#pragma unroll
            for (int q = 0; q < 4; q++) { accG[i][j][q] = 0.f; accU[i][j][q] = 0.f; }

    const int kchunks = DMODEL / BK;   // 64
    prefetch(0);

    for (int c = 0; c < kchunks; c++) {
        const int buf = c & 1;
        // store prefetched tile
        *(uint4*)&sAh[buf][ar][ac] = pah;
        *(uint4*)&sAl[buf][ar][ac] = pal;
        {
            const float bg[4] = {pbg.x, pbg.y, pbg.z, pbg.w};
            const float bu[4] = {pbu.x, pbu.y, pbu.z, pbu.w};
#pragma unroll
            for (int j = 0; j < 4; j++) {
                __nv_bfloat16 h, l;
                split1(bg[j], h, l);
                sBgh[buf][bn + j][bk] = h;
                sBgl[buf][bn + j][bk] = l;
                split1(bu[j], h, l);
                sBuh[buf][bn + j][bk] = h;
                sBul[buf][bn + j][bk] = l;
            }
        }
        __syncthreads();
        if (c + 1 < kchunks) prefetch(c + 1);

        uint32_t ah[2][4], al[2][4];
#pragma unroll
        for (int mt = 0; mt < 2; mt++) {
            const int mr = wm * 32 + mt * 16 + fr;
            ah[mt][0] = *(const uint32_t*)&sAh[buf][mr    ][fc    ];
            ah[mt][1] = *(const uint32_t*)&sAh[buf][mr + 8][fc    ];
            ah[mt][2] = *(const uint32_t*)&sAh[buf][mr    ][fc + 8];
            ah[mt][3] = *(const uint32_t*)&sAh[buf][mr + 8][fc + 8];
            al[mt][0] = *(const uint32_t*)&sAl[buf][mr    ][fc    ];
            al[mt][1] = *(const uint32_t*)&sAl[buf][mr + 8][fc    ];
            al[mt][2] = *(const uint32_t*)&sAl[buf][mr    ][fc + 8];
            al[mt][3] = *(const uint32_t*)&sAl[buf][mr + 8][fc + 8];
        }
#pragma unroll
        for (int nt = 0; nt < 4; nt++) {
            const int nr = wn * 32 + nt * 8 + fr;
            uint32_t bh0, bh1, bl0, bl1;
            bh0 = *(const uint32_t*)&sBgh[buf][nr][fc];
            bh1 = *(const uint32_t*)&sBgh[buf][nr][fc + 8];
            bl0 = *(const uint32_t*)&sBgl[buf][nr][fc];
            bl1 = *(const uint32_t*)&sBgl[buf][nr][fc + 8];
#pragma unroll
            for (int mt = 0; mt < 2; mt++) {
                MMA16816(accG[mt][nt], ah[mt], bh0, bh1);
                MMA16816(accG[mt][nt], ah[mt], bl0, bl1);
                MMA16816(accG[mt][nt], al[mt], bh0, bh1);
            }
            bh0 = *(const uint32_t*)&sBuh[buf][nr][fc];
            bh1 = *(const uint32_t*)&sBuh[buf][nr][fc + 8];
            bl0 = *(const uint32_t*)&sBul[buf][nr][fc];
            bl1 = *(const uint32_t*)&sBul[buf][nr][fc + 8];
#pragma unroll
            for (int mt = 0; mt < 2; mt++) {
                MMA16816(accU[mt][nt], ah[mt], bh0, bh1);
                MMA16816(accU[mt][nt], ah[mt], bl0, bl1);
                MMA16816(accU[mt][nt], al[mt], bh0, bh1);
            }
        }
        __syncthreads();   // readers done before next store to this buffer's twin
    }

    // ---- epilogue: act = silu(g) * u -> split bf16
#pragma unroll
    for (int mt = 0; mt < 2; mt++) {
#pragma unroll
        for (int half = 0; half < 2; half++) {
            const size_t slotrow =
                (size_t)(e * CAP + m0 + wm * 32 + mt * 16 + half * 8 + fr);
#pragma unroll
            for (int nt = 0; nt < 4; nt++) {
                const int gcol = n0 + wn * 32 + nt * 8 + fc;
                float gg0 = accG[mt][nt][half * 2 + 0];
                float gg1 = accG[mt][nt][half * 2 + 1];
                float uu0 = accU[mt][nt][half * 2 + 0];
                float uu1 = accU[mt][nt][half * 2 + 1];
                float a0 = (gg0 / (1.f + __expf(-gg0))) * uu0;
                float a1 = (gg1 / (1.f + __expf(-gg1))) * uu1;
                uint32_t hi, lo;
                split2(a0, a1, hi, lo);
                *(uint32_t*)&g_acth[slotrow * HDIM + gcol] = hi;
                *(uint32_t*)&g_actl[slotrow * HDIM + gcol] = lo;
            }
        }
    }
}

// ---------------- down GEMM: Y = ACT @ Wd[e] --------------------------------
__global__ void __launch_bounds__(256, 2) gemm_down_kernel(
        const float* __restrict__ Wd) {
    __shared__ __align__(16) __nv_bfloat16 sAh[2][BM][KP];
    __shared__ __align__(16) __nv_bfloat16 sAl[2][BM][KP];
    __shared__ __align__(16) __nv_bfloat16 sBh[2][BN][KP];
    __shared__ __align__(16) __nv_bfloat16 sBl[2][BN][KP];   // 36KB total

    const int e  = blockIdx.z;
    const int m0 = blockIdx.y * BM;
    if (m0 >= g_count[e]) return;
    const int n0 = blockIdx.x * BN;

    const size_t abase = (size_t)(e * CAP + m0) * HDIM;
    const float* Bd = Wd + (size_t)e * HDIM * DMODEL;

    const int tid  = threadIdx.x;
    const int lane = tid & 31, warp = tid >> 5;
    const int wm = warp >> 1, wn = warp & 1;
    const int fr = lane >> 2;
    const int fc = (lane & 3) * 2;

    const int ar = tid >> 1, ac = (tid & 1) * 8;
    const int bk = tid >> 4, bn = (tid & 15) * 4;

    uint4 pah, pal;
    float4 pb;
    auto prefetch = [&](int c) {
        const int k0 = c * BK;
        pah = *(const uint4*)(g_acth + abase + (size_t)ar * HDIM + k0 + ac);
        pal = *(const uint4*)(g_actl + abase + (size_t)ar * HDIM + k0 + ac);
        pb  = *(const float4*)(Bd + (size_t)(k0 + bk) * DMODEL + n0 + bn);
    };

    float acc[2][4][4];
#pragma unroll
    for (int i = 0; i < 2; i++)
#pragma unroll
        for (int j = 0; j < 4; j++)
#pragma unroll
            for (int q = 0; q < 4; q++) acc[i][j][q] = 0.f;

    const int kchunks = HDIM / BK;   // 176
    prefetch(0);

    for (int c = 0; c < kchunks; c++) {
        const int buf = c & 1;
        *(uint4*)&sAh[buf][ar][ac] = pah;
        *(uint4*)&sAl[buf][ar][ac] = pal;
        {
            const float bb[4] = {pb.x, pb.y, pb.z, pb.w};
#pragma unroll
            for (int j = 0; j < 4; j++) {
                __nv_bfloat16 h, l;
                split1(bb[j], h, l);
                sBh[buf][bn + j][bk] = h;
                sBl[buf][bn + j][bk] = l;
            }
        }
        __syncthreads();
        if (c + 1 < kchunks) prefetch(c + 1);

        uint32_t ah[2][4], al[2][4];
#pragma unroll
        for (int mt = 0; mt < 2; mt++) {
            const int mr = wm * 32 + mt * 16 + fr;
            ah[mt][0] = *(const uint32_t*)&sAh[buf][mr    ][fc    ];
            ah[mt][1] = *(const uint32_t*)&sAh[buf][mr + 8][fc    ];
            ah[mt][2] = *(const uint32_t*)&sAh[buf][mr    ][fc + 8];
            ah[mt][3] = *(const uint32_t*)&sAh[buf][mr + 8][fc + 8];
            al[mt][0] = *(const uint32_t*)&sAl[buf][mr    ][fc    ];
            al[mt][1] = *(const uint32_t*)&sAl[buf][mr + 8][fc    ];
            al[mt][2] = *(const uint32_t*)&sAl[buf][mr    ][fc + 8];
            al[mt][3] = *(const uint32_t*)&sAl[buf][mr + 8][fc + 8];
        }
#pragma unroll
        for (int nt = 0; nt < 4; nt++) {
            const int nr = wn * 32 + nt * 8 + fr;
            uint32_t bh0 = *(const uint32_t*)&sBh[buf][nr][fc];
            uint32_t bh1 = *(const uint32_t*)&sBh[buf][nr][fc + 8];
            uint32_t bl0 = *(const uint32_t*)&sBl[buf][nr][fc];
            uint32_t bl1 = *(const uint32_t*)&sBl[buf][nr][fc + 8];
#pragma unroll
            for (int mt = 0; mt < 2; mt++) {
                MMA16816(acc[mt][nt], ah[mt], bh0, bh1);
                MMA16816(acc[mt][nt], ah[mt], bl0, bl1);
                MMA16816(acc[mt][nt], al[mt], bh0, bh1);
            }
        }
        __syncthreads();
    }

#pragma unroll
    for (int mt = 0; mt < 2; mt++) {
#pragma unroll
        for (int half = 0; half < 2; half++) {
            const size_t slotrow =
                (size_t)(e * CAP + m0 + wm * 32 + mt * 16 + half * 8 + fr);
#pragma unroll
            for (int nt = 0; nt < 4; nt++) {
                const int gcol = n0 + wn * 32 + nt * 8 + fc;
                *(float2*)&g_Y[slotrow * DMODEL + gcol] =
                    make_float2(acc[mt][nt][half * 2 + 0],
                                acc[mt][nt][half * 2 + 1]);
            }
        }
    }
}

// ---------------- scatter back -----------------------------------------------
__global__ void scatter_kernel(const float* __restrict__ x,
                               const float* __restrict__ scores,
                               float* __restrict__ out) {
    int t = blockIdx.x;
    int i = threadIdx.x;
    int slot = g_slot_of_token[t];
    float4 v;
    if (slot < SLOTS) {
        v = *(const float4*)(g_Y + (size_t)slot * DMODEL + i * 4);
        float s = scores[t];
        v.x *= s; v.y *= s; v.z *= s; v.w *= s;
    } else {
        v = *(const float4*)(x + (size_t)t * DMODEL + i * 4);
    }
    *(float4*)(out + (size_t)t * DMODEL + i * 4) = v;
}

// -----------------------------------------------------------------------------
extern "C" void kernel_launch(void* const* d_in, const int* in_sizes, int n_in,
                              void* d_out, int out_size) {
    const float* x      = (const float*)d_in[0];
    const int*   idxw   = (const int*)d_in[1];
    const float* scores = (const float*)d_in[2];
    const float* Wg     = (const float*)d_in[3];
    const float* Wu     = (const float*)d_in[4];
    const float* Wd     = (const float*)d_in[5];
    float*       out    = (float*)d_out;

    route_kernel<<<1, 256>>>(idxw);
    gather_kernel<<<SLOTS, 256>>>(x);

    gemm_gu_kernel<<<dim3(HDIM / BN, CAP / BM, NEXP), 256>>>(Wg, Wu);
    gemm_down_kernel<<<dim3(DMODEL / BN, CAP / BM, NEXP), 256>>>(Wd);

    scatter_kernel<<<N_TOK, 256>>>(x, scores, out);
}

// round 9
// speedup vs baseline: 1.3690x; 1.3690x over previous
#include <cuda_runtime.h>
#include <cuda_bf16.h>
#include <cstdint>

// Problem constants
#define N_TOK  8192
#define DMODEL 1024
#define NEXP   8
#define HDIM   2816
#define CAP    1280
#define SLOTS  (NEXP * CAP)          // 10240

// ---------------- device scratch (~200 MB; statics MUST stay < ~270 MB) ----
__device__ int g_slot_of_token[N_TOK];
__device__ int g_token_of_slot[SLOTS];
__device__ int g_count[NEXP];
__device__ __align__(256) __nv_bfloat16 g_xh [(size_t)SLOTS * DMODEL];
__device__ __align__(256) __nv_bfloat16 g_xl [(size_t)SLOTS * DMODEL];
__device__ __align__(256) __nv_bfloat16 g_acth[(size_t)SLOTS * HDIM];
__device__ __align__(256) __nv_bfloat16 g_actl[(size_t)SLOTS * HDIM];
__device__ __align__(256) float g_Y[(size_t)SLOTS * DMODEL];

#define MMA16816(d, a, b0, b1) \
    asm volatile("mma.sync.aligned.m16n8k16.row.col.f32.bf16.bf16.f32 " \
                 "{%0,%1,%2,%3}, {%4,%5,%6,%7}, {%8,%9}, {%0,%1,%2,%3};" \
                 : "+f"((d)[0]), "+f"((d)[1]), "+f"((d)[2]), "+f"((d)[3]) \
                 : "r"((a)[0]), "r"((a)[1]), "r"((a)[2]), "r"((a)[3]), \
                   "r"(b0), "r"(b1))

// split two fp32 into packed bf16x2 hi and lo (lo = residual)
__device__ __forceinline__ void split2(float f0, float f1,
                                       uint32_t& hi, uint32_t& lo) {
    __nv_bfloat16 h0 = __float2bfloat16_rn(f0);
    __nv_bfloat16 h1 = __float2bfloat16_rn(f1);
    __nv_bfloat16 l0 = __float2bfloat16_rn(f0 - __bfloat162float(h0));
    __nv_bfloat16 l1 = __float2bfloat16_rn(f1 - __bfloat162float(h1));
    __nv_bfloat162 hp = __halves2bfloat162(h0, h1);
    __nv_bfloat162 lp = __halves2bfloat162(l0, l1);
    hi = *(uint32_t*)&hp; lo = *(uint32_t*)&lp;
}

// ---------------- routing (dtype-adaptive int32/int64) ----------------------
__global__ void route_kernel(const int* __restrict__ idxw) {
    __shared__ int s_any;
    int tid = threadIdx.x;
    if (tid == 0) s_any = 0;
    for (int s = tid; s < SLOTS; s += 256) g_token_of_slot[s] = -1;
    __syncthreads();
    int local = 0;
    for (int i = 2 * tid + 1; i < N_TOK; i += 512) local |= idxw[i];
    if (local) atomicOr(&s_any, 1);
    __syncthreads();
    const int stride = s_any ? 1 : 2;
    int warp = tid >> 5, lane = tid & 31;
    if (warp < NEXP) {
        int e = warp, cnt = 0;
        for (int base = 0; base < N_TOK; base += 32) {
            int t = base + lane;
            int ei = idxw[t * stride];
            bool m = (ei == e);
            unsigned mask = __ballot_sync(0xffffffffu, m);
            if (m) {
                int pos = cnt + __popc(mask & ((1u << lane) - 1u));
                if (pos < CAP) {
                    g_slot_of_token[t] = e * CAP + pos;
                    g_token_of_slot[e * CAP + pos] = t;
                } else {
                    g_slot_of_token[t] = SLOTS;
                }
            }
            cnt += __popc(mask);
        }
        if (lane == 0) g_count[e] = (cnt < CAP) ? cnt : CAP;
    }
}

// ---------------- gather tokens into split bf16 slot buffer ----------------
__global__ void gather_kernel(const float* __restrict__ x) {
    int s = blockIdx.x;
    int tok = g_token_of_slot[s];
    int i = threadIdx.x;              // 0..255 -> float4
    float4 v = make_float4(0.f, 0.f, 0.f, 0.f);
    if (tok >= 0) v = *(const float4*)(x + (size_t)tok * DMODEL + i * 4);
    uint32_t h01, l01, h23, l23;
    split2(v.x, v.y, h01, l01);
    split2(v.z, v.w, h23, l23);
    uint2 hv = make_uint2(h01, h23), lv = make_uint2(l01, l23);
    *(uint2*)(g_xh + (size_t)s * DMODEL + i * 4) = hv;
    *(uint2*)(g_xl + (size_t)s * DMODEL + i * 4) = lv;
}

// ---------------- GEMM tiling (R7 core + double buffering) -----------------
// BM=128, BN=64, BK=32; 256 threads = 8 warps (4m x 2n), warp tile 32x32.
// A: split bf16 in smem. B: fp32 in smem, hi/lo built in registers.
// Double-buffered smem: ONE __syncthreads per chunk.
#define BM 128
#define BN 64
#define BK 32
#define APAD 40   // bf16 row stride for A tiles
#define BPAD 68   // f32 row stride for B tiles

#define A_BUF_BYTES (BM * APAD * 2)            // 10240
#define B_BUF_BYTES (BK * BPAD * 4)            // 8704
#define SMEM_GU (4 * A_BUF_BYTES + 4 * B_BUF_BYTES)  // 75776
#define SMEM_DN (4 * A_BUF_BYTES + 2 * B_BUF_BYTES)  // 58368

// ---------------- fused gate+up GEMM ----------------------------------------
__global__ void __launch_bounds__(256, 2) gemm_gu_kernel(
        const float* __restrict__ Wg, const float* __restrict__ Wu) {
    extern __shared__ char smem[];
    typedef __nv_bfloat16 (*ATile)[BM][APAD];
    typedef float (*BTile)[BK][BPAD];
    ATile sAh = (ATile)(smem);
    ATile sAl = (ATile)(smem + 2 * A_BUF_BYTES);
    BTile sBg = (BTile)(smem + 4 * A_BUF_BYTES);
    BTile sBu = (BTile)(smem + 4 * A_BUF_BYTES + 2 * B_BUF_BYTES);

    const int e  = blockIdx.z;
    const int m0 = blockIdx.y * BM;
    if (m0 >= g_count[e]) return;
    const int n0 = blockIdx.x * BN;

    const size_t abase = (size_t)(e * CAP + m0) * DMODEL;
    const float* Bg = Wg + (size_t)e * DMODEL * HDIM;
    const float* Bu = Wu + (size_t)e * DMODEL * HDIM;

    const int tid  = threadIdx.x;
    const int lane = tid & 31, warp = tid >> 5;
    const int wm = warp >> 1, wn = warp & 1;
    const int fr = lane >> 2;
    const int fc = (lane & 3) * 2;

    // A loads: uint4 = 8 bf16; 128 rows x 4 chunks = 512 -> 2/thread
    const int ar0 = tid >> 2, ac0 = (tid & 3) * 8;
    const int ar1 = ar0 + 64;
    // B loads: float4; 32 rows x 16 chunks = 512 -> 2/thread per matrix
    const int br0 = tid >> 4, bc0 = (tid & 15) * 4;
    const int br1 = br0 + 16;

    uint4 pah0, pah1, pal0, pal1;
    float4 pbg0, pbg1, pbu0, pbu1;
    auto prefetch = [&](int c) {
        const int k0 = c * BK;
        pah0 = *(const uint4*)(g_xh + abase + (size_t)ar0 * DMODEL + k0 + ac0);
        pal0 = *(const uint4*)(g_xl + abase + (size_t)ar0 * DMODEL + k0 + ac0);
        pah1 = *(const uint4*)(g_xh + abase + (size_t)ar1 * DMODEL + k0 + ac0);
        pal1 = *(const uint4*)(g_xl + abase + (size_t)ar1 * DMODEL + k0 + ac0);
        pbg0 = *(const float4*)(Bg + (size_t)(k0 + br0) * HDIM + n0 + bc0);
        pbg1 = *(const float4*)(Bg + (size_t)(k0 + br1) * HDIM + n0 + bc0);
        pbu0 = *(const float4*)(Bu + (size_t)(k0 + br0) * HDIM + n0 + bc0);
        pbu1 = *(const float4*)(Bu + (size_t)(k0 + br1) * HDIM + n0 + bc0);
    };
    auto store = [&](int buf) {
        *(uint4*)&sAh[buf][ar0][ac0] = pah0;
        *(uint4*)&sAl[buf][ar0][ac0] = pal0;
        *(uint4*)&sAh[buf][ar1][ac0] = pah1;
        *(uint4*)&sAl[buf][ar1][ac0] = pal1;
        *(float4*)&sBg[buf][br0][bc0] = pbg0;
        *(float4*)&sBg[buf][br1][bc0] = pbg1;
        *(float4*)&sBu[buf][br0][bc0] = pbu0;
        *(float4*)&sBu[buf][br1][bc0] = pbu1;
    };

    float accG[2][4][4], accU[2][4][4];
#pragma unroll
    for (int i = 0; i < 2; i++)
#pragma unroll
        for (int j = 0; j < 4; j++)
#pragma unroll
            for (int q = 0; q < 4; q++) { accG[i][j][q] = 0.f; accU[i][j][q] = 0.f; }

    const int kchunks = DMODEL / BK;   // 32
    prefetch(0);
    store(0);
    prefetch(1);
    __syncthreads();

    for (int c = 0; c < kchunks; c++) {
        const int buf = c & 1;
        if (c + 1 < kchunks) store(buf ^ 1);   // other buffer; current readers ok
        if (c + 2 < kchunks) prefetch(c + 2);

#pragma unroll
        for (int ks = 0; ks < 2; ks++) {
            const int ko = ks * 16 + fc;
            uint32_t ah[2][4], al[2][4];
#pragma unroll
            for (int mt = 0; mt < 2; mt++) {
                const int mr = wm * 32 + mt * 16 + fr;
                ah[mt][0] = *(const uint32_t*)&sAh[buf][mr    ][ko    ];
                ah[mt][1] = *(const uint32_t*)&sAh[buf][mr + 8][ko    ];
                ah[mt][2] = *(const uint32_t*)&sAh[buf][mr    ][ko + 8];
                ah[mt][3] = *(const uint32_t*)&sAh[buf][mr + 8][ko + 8];
                al[mt][0] = *(const uint32_t*)&sAl[buf][mr    ][ko    ];
                al[mt][1] = *(const uint32_t*)&sAl[buf][mr + 8][ko    ];
                al[mt][2] = *(const uint32_t*)&sAl[buf][mr    ][ko + 8];
                al[mt][3] = *(const uint32_t*)&sAl[buf][mr + 8][ko + 8];
            }
#pragma unroll
            for (int nt = 0; nt < 4; nt++) {
                const int nr = wn * 32 + nt * 8 + fr;
                uint32_t bh0, bl0, bh1, bl1;
                split2(sBg[buf][ko][nr],     sBg[buf][ko + 1][nr], bh0, bl0);
                split2(sBg[buf][ko + 8][nr], sBg[buf][ko + 9][nr], bh1, bl1);
#pragma unroll
                for (int mt = 0; mt < 2; mt++) {
                    MMA16816(accG[mt][nt], ah[mt], bh0, bh1);
                    MMA16816(accG[mt][nt], ah[mt], bl0, bl1);
                    MMA16816(accG[mt][nt], al[mt], bh0, bh1);
                }
                split2(sBu[buf][ko][nr],     sBu[buf][ko + 1][nr], bh0, bl0);
                split2(sBu[buf][ko + 8][nr], sBu[buf][ko + 9][nr], bh1, bl1);
#pragma unroll
                for (int mt = 0; mt < 2; mt++) {
                    MMA16816(accU[mt][nt], ah[mt], bh0, bh1);
                    MMA16816(accU[mt][nt], ah[mt], bl0, bl1);
                    MMA16816(accU[mt][nt], al[mt], bh0, bh1);
                }
            }
        }
        __syncthreads();
    }

    // ---- epilogue: act = silu(g) * u -> split bf16
#pragma unroll
    for (int mt = 0; mt < 2; mt++) {
#pragma unroll
        for (int half = 0; half < 2; half++) {
            const size_t slotrow =
                (size_t)(e * CAP + m0 + wm * 32 + mt * 16 + half * 8 + fr);
#pragma unroll
            for (int nt = 0; nt < 4; nt++) {
                const int gcol = n0 + wn * 32 + nt * 8 + fc;
                float gg0 = accG[mt][nt][half * 2 + 0];
                float gg1 = accG[mt][nt][half * 2 + 1];
                float uu0 = accU[mt][nt][half * 2 + 0];
                float uu1 = accU[mt][nt][half * 2 + 1];
                float a0 = (gg0 / (1.f + __expf(-gg0))) * uu0;
                float a1 = (gg1 / (1.f + __expf(-gg1))) * uu1;
                uint32_t hi, lo;
                split2(a0, a1, hi, lo);
                *(uint32_t*)&g_acth[slotrow * HDIM + gcol] = hi;
                *(uint32_t*)&g_actl[slotrow * HDIM + gcol] = lo;
            }
        }
    }
}

// ---------------- down GEMM: Y = ACT @ Wd[e] --------------------------------
__global__ void __launch_bounds__(256, 2) gemm_down_kernel(
        const float* __restrict__ Wd) {
    extern __shared__ char smem[];
    typedef __nv_bfloat16 (*ATile)[BM][APAD];
    typedef float (*BTile)[BK][BPAD];
    ATile sAh = (ATile)(smem);
    ATile sAl = (ATile)(smem + 2 * A_BUF_BYTES);
    BTile sB  = (BTile)(smem + 4 * A_BUF_BYTES);

    const int e  = blockIdx.z;
    const int m0 = blockIdx.y * BM;
    if (m0 >= g_count[e]) return;
    const int n0 = blockIdx.x * BN;

    const size_t abase = (size_t)(e * CAP + m0) * HDIM;
    const float* Bd = Wd + (size_t)e * HDIM * DMODEL;

    const int tid  = threadIdx.x;
    const int lane = tid & 31, warp = tid >> 5;
    const int wm = warp >> 1, wn = warp & 1;
    const int fr = lane >> 2;
    const int fc = (lane & 3) * 2;

    const int ar0 = tid >> 2, ac0 = (tid & 3) * 8;
    const int ar1 = ar0 + 64;
    const int br0 = tid >> 4, bc0 = (tid & 15) * 4;
    const int br1 = br0 + 16;

    uint4 pah0, pah1, pal0, pal1;
    float4 pb0, pb1;
    auto prefetch = [&](int c) {
        const int k0 = c * BK;
        pah0 = *(const uint4*)(g_acth + abase + (size_t)ar0 * HDIM + k0 + ac0);
        pal0 = *(const uint4*)(g_actl + abase + (size_t)ar0 * HDIM + k0 + ac0);
        pah1 = *(const uint4*)(g_acth + abase + (size_t)ar1 * HDIM + k0 + ac0);
        pal1 = *(const uint4*)(g_actl + abase + (size_t)ar1 * HDIM + k0 + ac0);
        pb0 = *(const float4*)(Bd + (size_t)(k0 + br0) * DMODEL + n0 + bc0);
        pb1 = *(const float4*)(Bd + (size_t)(k0 + br1) * DMODEL + n0 + bc0);
    };
    auto store = [&](int buf) {
        *(uint4*)&sAh[buf][ar0][ac0] = pah0;
        *(uint4*)&sAl[buf][ar0][ac0] = pal0;
        *(uint4*)&sAh[buf][ar1][ac0] = pah1;
        *(uint4*)&sAl[buf][ar1][ac0] = pal1;
        *(float4*)&sB[buf][br0][bc0] = pb0;
        *(float4*)&sB[buf][br1][bc0] = pb1;
    };

    float acc[2][4][4];
#pragma unroll
    for (int i = 0; i < 2; i++)
#pragma unroll
        for (int j = 0; j < 4; j++)
#pragma unroll
            for (int q = 0; q < 4; q++) acc[i][j][q] = 0.f;

    const int kchunks = HDIM / BK;   // 88
    prefetch(0);
    store(0);
    prefetch(1);
    __syncthreads();

    for (int c = 0; c < kchunks; c++) {
        const int buf = c & 1;
        if (c + 1 < kchunks) store(buf ^ 1);
        if (c + 2 < kchunks) prefetch(c + 2);

#pragma unroll
        for (int ks = 0; ks < 2; ks++) {
            const int ko = ks * 16 + fc;
            uint32_t ah[2][4], al[2][4];
#pragma unroll
            for (int mt = 0; mt < 2; mt++) {
                const int mr = wm * 32 + mt * 16 + fr;
                ah[mt][0] = *(const uint32_t*)&sAh[buf][mr    ][ko    ];
                ah[mt][1] = *(const uint32_t*)&sAh[buf][mr + 8][ko    ];
                ah[mt][2] = *(const uint32_t*)&sAh[buf][mr    ][ko + 8];
                ah[mt][3] = *(const uint32_t*)&sAh[buf][mr + 8][ko + 8];
                al[mt][0] = *(const uint32_t*)&sAl[buf][mr    ][ko    ];
                al[mt][1] = *(const uint32_t*)&sAl[buf][mr + 8][ko    ];
                al[mt][2] = *(const uint32_t*)&sAl[buf][mr    ][ko + 8];
                al[mt][3] = *(const uint32_t*)&sAl[buf][mr + 8][ko + 8];
            }
#pragma unroll
            for (int nt = 0; nt < 4; nt++) {
                const int nr = wn * 32 + nt * 8 + fr;
                uint32_t bh0, bl0, bh1, bl1;
                split2(sB[buf][ko][nr],     sB[buf][ko + 1][nr], bh0, bl0);
                split2(sB[buf][ko + 8][nr], sB[buf][ko + 9][nr], bh1, bl1);
#pragma unroll
                for (int mt = 0; mt < 2; mt++) {
                    MMA16816(acc[mt][nt], ah[mt], bh0, bh1);
                    MMA16816(acc[mt][nt], ah[mt], bl0, bl1);
                    MMA16816(acc[mt][nt], al[mt], bh0, bh1);
                }
            }
        }
        __syncthreads();
    }

#pragma unroll
    for (int mt = 0; mt < 2; mt++) {
#pragma unroll
        for (int half = 0; half < 2; half++) {
            const size_t slotrow =
                (size_t)(e * CAP + m0 + wm * 32 + mt * 16 + half * 8 + fr);
#pragma unroll
            for (int nt = 0; nt < 4; nt++) {
                const int gcol = n0 + wn * 32 + nt * 8 + fc;
                *(float2*)&g_Y[slotrow * DMODEL + gcol] =
                    make_float2(acc[mt][nt][half * 2 + 0],
                                acc[mt][nt][half * 2 + 1]);
            }
        }
    }
}

// ---------------- scatter back -----------------------------------------------
__global__ void scatter_kernel(const float* __restrict__ x,
                               const float* __restrict__ scores,
                               float* __restrict__ out) {
    int t = blockIdx.x;
    int i = threadIdx.x;
    int slot = g_slot_of_token[t];
    float4 v;
    if (slot < SLOTS) {
        v = *(const float4*)(g_Y + (size_t)slot * DMODEL + i * 4);
        float s = scores[t];
        v.x *= s; v.y *= s; v.z *= s; v.w *= s;
    } else {
        v = *(const float4*)(x + (size_t)t * DMODEL + i * 4);
    }
    *(float4*)(out + (size_t)t * DMODEL + i * 4) = v;
}

// -----------------------------------------------------------------------------
extern "C" void kernel_launch(void* const* d_in, const int* in_sizes, int n_in,
                              void* d_out, int out_size) {
    const float* x      = (const float*)d_in[0];
    const int*   idxw   = (const int*)d_in[1];
    const float* scores = (const float*)d_in[2];
    const float* Wg     = (const float*)d_in[3];
    const float* Wu     = (const float*)d_in[4];
    const float* Wd     = (const float*)d_in[5];
    float*       out    = (float*)d_out;

    cudaFuncSetAttribute(gemm_gu_kernel,
                         cudaFuncAttributeMaxDynamicSharedMemorySize, SMEM_GU);
    cudaFuncSetAttribute(gemm_down_kernel,
                         cudaFuncAttributeMaxDynamicSharedMemorySize, SMEM_DN);

    route_kernel<<<1, 256>>>(idxw);
    gather_kernel<<<SLOTS, 256>>>(x);

    gemm_gu_kernel<<<dim3(HDIM / BN, CAP / BM, NEXP), 256, SMEM_GU>>>(Wg, Wu);
    gemm_down_kernel<<<dim3(DMODEL / BN, CAP / BM, NEXP), 256, SMEM_DN>>>(Wd);

    scatter_kernel<<<N_TOK, 256>>>(x, scores, out);
}

// round 10
// speedup vs baseline: 1.7155x; 1.2531x over previous
#include <cuda_runtime.h>
#include <cuda_bf16.h>
#include <cstdint>

// Problem constants
#define N_TOK  8192
#define DMODEL 1024
#define NEXP   8
#define HDIM   2816
#define CAP    1280
#define SLOTS  (NEXP * CAP)          // 10240

// ---------------- device scratch (~200 MB; statics MUST stay < ~270 MB) ----
__device__ int g_slot_of_token[N_TOK];
__device__ int g_token_of_slot[SLOTS];
__device__ int g_count[NEXP];
__device__ __align__(256) __nv_bfloat16 g_xh [(size_t)SLOTS * DMODEL];
__device__ __align__(256) __nv_bfloat16 g_xl [(size_t)SLOTS * DMODEL];
__device__ __align__(256) __nv_bfloat16 g_acth[(size_t)SLOTS * HDIM];
__device__ __align__(256) __nv_bfloat16 g_actl[(size_t)SLOTS * HDIM];
__device__ __align__(256) float g_Y[(size_t)SLOTS * DMODEL];

__device__ __forceinline__ uint32_t smem_u32(const void* p) {
    uint32_t a;
    asm("{ .reg .u64 t; cvta.to.shared.u64 t, %1; cvt.u32.u64 %0, t; }"
        : "=r"(a) : "l"(p));
    return a;
}

#define MMA16816(d, a, b0, b1) \
    asm volatile("mma.sync.aligned.m16n8k16.row.col.f32.bf16.bf16.f32 " \
                 "{%0,%1,%2,%3}, {%4,%5,%6,%7}, {%8,%9}, {%0,%1,%2,%3};" \
                 : "+f"((d)[0]), "+f"((d)[1]), "+f"((d)[2]), "+f"((d)[3]) \
                 : "r"((a)[0]), "r"((a)[1]), "r"((a)[2]), "r"((a)[3]), \
                   "r"(b0), "r"(b1))

#define LDSM4(r, a) \
    asm volatile("ldmatrix.sync.aligned.m8n8.x4.shared.b16 {%0,%1,%2,%3}, [%4];" \
                 : "=r"((r)[0]), "=r"((r)[1]), "=r"((r)[2]), "=r"((r)[3]) : "r"(a))
#define LDSM4T(r, a) \
    asm volatile("ldmatrix.sync.aligned.m8n8.x4.trans.shared.b16 {%0,%1,%2,%3}, [%4];" \
                 : "=r"((r)[0]), "=r"((r)[1]), "=r"((r)[2]), "=r"((r)[3]) : "r"(a))

// split two fp32 into packed bf16x2 hi and lo (lo = residual)
__device__ __forceinline__ void split2(float f0, float f1,
                                       uint32_t& hi, uint32_t& lo) {
    __nv_bfloat16 h0 = __float2bfloat16_rn(f0);
    __nv_bfloat16 h1 = __float2bfloat16_rn(f1);
    __nv_bfloat16 l0 = __float2bfloat16_rn(f0 - __bfloat162float(h0));
    __nv_bfloat16 l1 = __float2bfloat16_rn(f1 - __bfloat162float(h1));
    __nv_bfloat162 hp = __halves2bfloat162(h0, h1);
    __nv_bfloat162 lp = __halves2bfloat162(l0, l1);
    hi = *(uint32_t*)&hp; lo = *(uint32_t*)&lp;
}

// ---------------- routing (dtype-adaptive int32/int64) ----------------------
__global__ void route_kernel(const int* __restrict__ idxw) {
    __shared__ int s_any;
    int tid = threadIdx.x;
    if (tid == 0) s_any = 0;
    for (int s = tid; s < SLOTS; s += 256) g_token_of_slot[s] = -1;
    __syncthreads();
    int local = 0;
    for (int i = 2 * tid + 1; i < N_TOK; i += 512) local |= idxw[i];
    if (local) atomicOr(&s_any, 1);
    __syncthreads();
    const int stride = s_any ? 1 : 2;
    int warp = tid >> 5, lane = tid & 31;
    if (warp < NEXP) {
        int e = warp, cnt = 0;
        for (int base = 0; base < N_TOK; base += 32) {
            int t = base + lane;
            int ei = idxw[t * stride];
            bool m = (ei == e);
            unsigned mask = __ballot_sync(0xffffffffu, m);
            if (m) {
                int pos = cnt + __popc(mask & ((1u << lane) - 1u));
                if (pos < CAP) {
                    g_slot_of_token[t] = e * CAP + pos;
                    g_token_of_slot[e * CAP + pos] = t;
                } else {
                    g_slot_of_token[t] = SLOTS;
                }
            }
            cnt += __popc(mask);
        }
        if (lane == 0) g_count[e] = (cnt < CAP) ? cnt : CAP;
    }
}

// ---------------- gather tokens into split bf16 slot buffer ----------------
__global__ void gather_kernel(const float* __restrict__ x) {
    int s = blockIdx.x;
    int tok = g_token_of_slot[s];
    int i = threadIdx.x;              // 0..255 -> float4
    float4 v = make_float4(0.f, 0.f, 0.f, 0.f);
    if (tok >= 0) v = *(const float4*)(x + (size_t)tok * DMODEL + i * 4);
    uint32_t h01, l01, h23, l23;
    split2(v.x, v.y, h01, l01);
    split2(v.z, v.w, h23, l23);
    uint2 hv = make_uint2(h01, h23), lv = make_uint2(l01, l23);
    *(uint2*)(g_xh + (size_t)s * DMODEL + i * 4) = hv;
    *(uint2*)(g_xl + (size_t)s * DMODEL + i * 4) = lv;
}

// ---------------- GEMM tiling ------------------------------------------------
// BM=128, BN=64, BK=32; 256 threads = 8 warps (4m x 2n), warp tile 32x32.
// A: split bf16 [BM][40] (80B rows -> ldmatrix conflict-free).
// B: split bf16 K-major [BK][72] (144B rows -> ldmatrix.trans conflict-free),
//    split from fp32 in the STORE phase (vectorized STS.64).
// Double buffer, one __syncthreads per chunk, register prefetch of c+2.
#define BM 128
#define BN 64
#define BK 32
#define APAD 40
#define BNP 72

#define A_BUF (BM * APAD * 2)                 // 10240 bytes per buffer
#define B_BUF (BK * BNP * 2)                  // 4608 bytes per buffer
#define OFF_AL (2 * A_BUF)                    // 20480
#define OFF_B0 (4 * A_BUF)                    // 40960
// gu: Bgh @OFF_B0, Bgl +2*B_BUF, Buh +4*B_BUF, Bul +6*B_BUF
#define SMEM_GU (OFF_B0 + 8 * B_BUF)          // 77824
// down: Bh @OFF_B0, Bl +2*B_BUF
#define SMEM_DN (OFF_B0 + 4 * B_BUF)          // 59392

// ---------------- fused gate+up GEMM ----------------------------------------
__global__ void __launch_bounds__(256, 2) gemm_gu_kernel(
        const float* __restrict__ Wg, const float* __restrict__ Wu) {
    extern __shared__ char smem[];

    const int e  = blockIdx.z;
    const int m0 = blockIdx.y * BM;
    if (m0 >= g_count[e]) return;
    const int n0 = blockIdx.x * BN;

    const size_t abase = (size_t)(e * CAP + m0) * DMODEL;
    const float* Bg = Wg + (size_t)e * DMODEL * HDIM;
    const float* Bu = Wu + (size_t)e * DMODEL * HDIM;

    const int tid  = threadIdx.x;
    const int lane = tid & 31, warp = tid >> 5;
    const int wm = warp >> 1, wn = warp & 1;
    const int fr = lane >> 2;
    const int fc = (lane & 3) * 2;

    const uint32_t sb = smem_u32(smem);
    // ldmatrix per-thread base offsets
    const uint32_t aoff = (uint32_t)(wm * 32 + (lane & 15)) * (APAD * 2)
                        + (uint32_t)(lane >> 4) * 16;
    const uint32_t boff = (uint32_t)(lane & 15) * (BNP * 2)
                        + (uint32_t)(wn * 32 + (lane >> 4) * 8) * 2;

    // global load assignments
    const int ar0 = tid >> 2, ac0 = (tid & 3) * 8;   // A: uint4 (8 bf16)
    const int ar1 = ar0 + 64;
    const int br0 = tid >> 4, bc0 = (tid & 15) * 4;  // B: float4
    const int br1 = br0 + 16;

    uint4 pah0, pah1, pal0, pal1;
    float4 pbg0, pbg1, pbu0, pbu1;
    auto prefetch = [&](int c) {
        const int k0 = c * BK;
        pah0 = *(const uint4*)(g_xh + abase + (size_t)ar0 * DMODEL + k0 + ac0);
        pal0 = *(const uint4*)(g_xl + abase + (size_t)ar0 * DMODEL + k0 + ac0);
        pah1 = *(const uint4*)(g_xh + abase + (size_t)ar1 * DMODEL + k0 + ac0);
        pal1 = *(const uint4*)(g_xl + abase + (size_t)ar1 * DMODEL + k0 + ac0);
        pbg0 = *(const float4*)(Bg + (size_t)(k0 + br0) * HDIM + n0 + bc0);
        pbg1 = *(const float4*)(Bg + (size_t)(k0 + br1) * HDIM + n0 + bc0);
        pbu0 = *(const float4*)(Bu + (size_t)(k0 + br0) * HDIM + n0 + bc0);
        pbu1 = *(const float4*)(Bu + (size_t)(k0 + br1) * HDIM + n0 + bc0);
    };
    auto store = [&](int buf) {
        __nv_bfloat16* pAh = (__nv_bfloat16*)(smem + buf * A_BUF);
        __nv_bfloat16* pAl = (__nv_bfloat16*)(smem + OFF_AL + buf * A_BUF);
        *(uint4*)&pAh[ar0 * APAD + ac0] = pah0;
        *(uint4*)&pAl[ar0 * APAD + ac0] = pal0;
        *(uint4*)&pAh[ar1 * APAD + ac0] = pah1;
        *(uint4*)&pAl[ar1 * APAD + ac0] = pal1;
        __nv_bfloat16* pgh = (__nv_bfloat16*)(smem + OFF_B0 + buf * B_BUF);
        __nv_bfloat16* pgl = (__nv_bfloat16*)(smem + OFF_B0 + 2 * B_BUF + buf * B_BUF);
        __nv_bfloat16* puh = (__nv_bfloat16*)(smem + OFF_B0 + 4 * B_BUF + buf * B_BUF);
        __nv_bfloat16* pul = (__nv_bfloat16*)(smem + OFF_B0 + 6 * B_BUF + buf * B_BUF);
        uint32_t h01, l01, h23, l23;
        split2(pbg0.x, pbg0.y, h01, l01); split2(pbg0.z, pbg0.w, h23, l23);
        *(uint2*)&pgh[br0 * BNP + bc0] = make_uint2(h01, h23);
        *(uint2*)&pgl[br0 * BNP + bc0] = make_uint2(l01, l23);
        split2(pbg1.x, pbg1.y, h01, l01); split2(pbg1.z, pbg1.w, h23, l23);
        *(uint2*)&pgh[br1 * BNP + bc0] = make_uint2(h01, h23);
        *(uint2*)&pgl[br1 * BNP + bc0] = make_uint2(l01, l23);
        split2(pbu0.x, pbu0.y, h01, l01); split2(pbu0.z, pbu0.w, h23, l23);
        *(uint2*)&puh[br0 * BNP + bc0] = make_uint2(h01, h23);
        *(uint2*)&pul[br0 * BNP + bc0] = make_uint2(l01, l23);
        split2(pbu1.x, pbu1.y, h01, l01); split2(pbu1.z, pbu1.w, h23, l23);
        *(uint2*)&puh[br1 * BNP + bc0] = make_uint2(h01, h23);
        *(uint2*)&pul[br1 * BNP + bc0] = make_uint2(l01, l23);
    };

    float accG[2][4][4], accU[2][4][4];
#pragma unroll
    for (int i = 0; i < 2; i++)
#pragma unroll
        for (int j = 0; j < 4; j++)
#pragma unroll
            for (int q = 0; q < 4; q++) { accG[i][j][q] = 0.f; accU[i][j][q] = 0.f; }

    const int kchunks = DMODEL / BK;   // 32
    prefetch(0);
    store(0);
    prefetch(1);
    __syncthreads();

    for (int c = 0; c < kchunks; c++) {
        const int buf = c & 1;
        if (c + 1 < kchunks) store(buf ^ 1);
        if (c + 2 < kchunks) prefetch(c + 2);

        const uint32_t uAh = sb + buf * A_BUF + aoff;
        const uint32_t uAl = sb + OFF_AL + buf * A_BUF + aoff;
        const uint32_t uBg = sb + OFF_B0 + buf * B_BUF + boff;
        const uint32_t uBgl = uBg + 2 * B_BUF;
        const uint32_t uBu = uBg + 4 * B_BUF;
        const uint32_t uBul = uBg + 6 * B_BUF;

#pragma unroll
        for (int ks = 0; ks < 2; ks++) {
            uint32_t ah[2][4], al[2][4];
#pragma unroll
            for (int mt = 0; mt < 2; mt++) {
                LDSM4(ah[mt], uAh + mt * (16 * APAD * 2) + ks * 32);
                LDSM4(al[mt], uAl + mt * (16 * APAD * 2) + ks * 32);
            }
            uint32_t bgh[4][2], bgl[4][2], buh[4][2], bul[4][2];
#pragma unroll
            for (int ng = 0; ng < 2; ng++) {
                uint32_t r[4];
                const uint32_t ko = ks * (16 * BNP * 2) + ng * 32;
                LDSM4T(r, uBg + ko);
                bgh[2*ng][0]=r[0]; bgh[2*ng][1]=r[1]; bgh[2*ng+1][0]=r[2]; bgh[2*ng+1][1]=r[3];
                LDSM4T(r, uBgl + ko);
                bgl[2*ng][0]=r[0]; bgl[2*ng][1]=r[1]; bgl[2*ng+1][0]=r[2]; bgl[2*ng+1][1]=r[3];
                LDSM4T(r, uBu + ko);
                buh[2*ng][0]=r[0]; buh[2*ng][1]=r[1]; buh[2*ng+1][0]=r[2]; buh[2*ng+1][1]=r[3];
                LDSM4T(r, uBul + ko);
                bul[2*ng][0]=r[0]; bul[2*ng][1]=r[1]; bul[2*ng+1][0]=r[2]; bul[2*ng+1][1]=r[3];
            }
#pragma unroll
            for (int nt = 0; nt < 4; nt++)
#pragma unroll
                for (int mt = 0; mt < 2; mt++) {
                    MMA16816(accG[mt][nt], ah[mt], bgh[nt][0], bgh[nt][1]);
                    MMA16816(accG[mt][nt], ah[mt], bgl[nt][0], bgl[nt][1]);
                    MMA16816(accG[mt][nt], al[mt], bgh[nt][0], bgh[nt][1]);
                    MMA16816(accU[mt][nt], ah[mt], buh[nt][0], buh[nt][1]);
                    MMA16816(accU[mt][nt], ah[mt], bul[nt][0], bul[nt][1]);
                    MMA16816(accU[mt][nt], al[mt], buh[nt][0], buh[nt][1]);
                }
        }
        __syncthreads();
    }

    // ---- epilogue: act = silu(g) * u -> split bf16
#pragma unroll
    for (int mt = 0; mt < 2; mt++) {
#pragma unroll
        for (int half = 0; half < 2; half++) {
            const size_t slotrow =
                (size_t)(e * CAP + m0 + wm * 32 + mt * 16 + half * 8 + fr);
#pragma unroll
            for (int nt = 0; nt < 4; nt++) {
                const int gcol = n0 + wn * 32 + nt * 8 + fc;
                float gg0 = accG[mt][nt][half * 2 + 0];
                float gg1 = accG[mt][nt][half * 2 + 1];
                float uu0 = accU[mt][nt][half * 2 + 0];
                float uu1 = accU[mt][nt][half * 2 + 1];
                float a0 = (gg0 / (1.f + __expf(-gg0))) * uu0;
                float a1 = (gg1 / (1.f + __expf(-gg1))) * uu1;
                uint32_t hi, lo;
                split2(a0, a1, hi, lo);
                *(uint32_t*)&g_acth[slotrow * HDIM + gcol] = hi;
                *(uint32_t*)&g_actl[slotrow * HDIM + gcol] = lo;
            }
        }
    }
}

// ---------------- down GEMM: Y = ACT @ Wd[e] --------------------------------
__global__ void __launch_bounds__(256, 2) gemm_down_kernel(
        const float* __restrict__ Wd) {
    extern __shared__ char smem[];

    const int e  = blockIdx.z;
    const int m0 = blockIdx.y * BM;
    if (m0 >= g_count[e]) return;
    const int n0 = blockIdx.x * BN;

    const size_t abase = (size_t)(e * CAP + m0) * HDIM;
    const float* Bd = Wd + (size_t)e * HDIM * DMODEL;

    const int tid  = threadIdx.x;
    const int lane = tid & 31, warp = tid >> 5;
    const int wm = warp >> 1, wn = warp & 1;
    const int fr = lane >> 2;
    const int fc = (lane & 3) * 2;

    const uint32_t sb = smem_u32(smem);
    const uint32_t aoff = (uint32_t)(wm * 32 + (lane & 15)) * (APAD * 2)
                        + (uint32_t)(lane >> 4) * 16;
    const uint32_t boff = (uint32_t)(lane & 15) * (BNP * 2)
                        + (uint32_t)(wn * 32 + (lane >> 4) * 8) * 2;

    const int ar0 = tid >> 2, ac0 = (tid & 3) * 8;
    const int ar1 = ar0 + 64;
    const int br0 = tid >> 4, bc0 = (tid & 15) * 4;
    const int br1 = br0 + 16;

    uint4 pah0, pah1, pal0, pal1;
    float4 pb0, pb1;
    auto prefetch = [&](int c) {
        const int k0 = c * BK;
        pah0 = *(const uint4*)(g_acth + abase + (size_t)ar0 * HDIM + k0 + ac0);
        pal0 = *(const uint4*)(g_actl + abase + (size_t)ar0 * HDIM + k0 + ac0);
        pah1 = *(const uint4*)(g_acth + abase + (size_t)ar1 * HDIM + k0 + ac0);
        pal1 = *(const uint4*)(g_actl + abase + (size_t)ar1 * HDIM + k0 + ac0);
        pb0 = *(const float4*)(Bd + (size_t)(k0 + br0) * DMODEL + n0 + bc0);
        pb1 = *(const float4*)(Bd + (size_t)(k0 + br1) * DMODEL + n0 + bc0);
    };
    auto store = [&](int buf) {
        __nv_bfloat16* pAh = (__nv_bfloat16*)(smem + buf * A_BUF);
        __nv_bfloat16* pAl = (__nv_bfloat16*)(smem + OFF_AL + buf * A_BUF);
        *(uint4*)&pAh[ar0 * APAD + ac0] = pah0;
        *(uint4*)&pAl[ar0 * APAD + ac0] = pal0;
        *(uint4*)&pAh[ar1 * APAD + ac0] = pah1;
        *(uint4*)&pAl[ar1 * APAD + ac0] = pal1;
        __nv_bfloat16* pBh = (__nv_bfloat16*)(smem + OFF_B0 + buf * B_BUF);
        __nv_bfloat16* pBl = (__nv_bfloat16*)(smem + OFF_B0 + 2 * B_BUF + buf * B_BUF);
        uint32_t h01, l01, h23, l23;
        split2(pb0.x, pb0.y, h01, l01); split2(pb0.z, pb0.w, h23, l23);
        *(uint2*)&pBh[br0 * BNP + bc0] = make_uint2(h01, h23);
        *(uint2*)&pBl[br0 * BNP + bc0] = make_uint2(l01, l23);
        split2(pb1.x, pb1.y, h01, l01); split2(pb1.z, pb1.w, h23, l23);
        *(uint2*)&pBh[br1 * BNP + bc0] = make_uint2(h01, h23);
        *(uint2*)&pBl[br1 * BNP + bc0] = make_uint2(l01, l23);
    };

    float acc[2][4][4];
#pragma unroll
    for (int i = 0; i < 2; i++)
#pragma unroll
        for (int j = 0; j < 4; j++)
#pragma unroll
            for (int q = 0; q < 4; q++) acc[i][j][q] = 0.f;

    const int kchunks = HDIM / BK;   // 88
    prefetch(0);
    store(0);
    prefetch(1);
    __syncthreads();

    for (int c = 0; c < kchunks; c++) {
        const int buf = c & 1;
        if (c + 1 < kchunks) store(buf ^ 1);
        if (c + 2 < kchunks) prefetch(c + 2);

        const uint32_t uAh = sb + buf * A_BUF + aoff;
        const uint32_t uAl = sb + OFF_AL + buf * A_BUF + aoff;
        const uint32_t uBh = sb + OFF_B0 + buf * B_BUF + boff;
        const uint32_t uBl = uBh + 2 * B_BUF;

#pragma unroll
        for (int ks = 0; ks < 2; ks++) {
            uint32_t ah[2][4], al[2][4];
#pragma unroll
            for (int mt = 0; mt < 2; mt++) {
                LDSM4(ah[mt], uAh + mt * (16 * APAD * 2) + ks * 32);
                LDSM4(al[mt], uAl + mt * (16 * APAD * 2) + ks * 32);
            }
            uint32_t bh[4][2], bl[4][2];
#pragma unroll
            for (int ng = 0; ng < 2; ng++) {
                uint32_t r[4];
                const uint32_t ko = ks * (16 * BNP * 2) + ng * 32;
                LDSM4T(r, uBh + ko);
                bh[2*ng][0]=r[0]; bh[2*ng][1]=r[1]; bh[2*ng+1][0]=r[2]; bh[2*ng+1][1]=r[3];
                LDSM4T(r, uBl + ko);
                bl[2*ng][0]=r[0]; bl[2*ng][1]=r[1]; bl[2*ng+1][0]=r[2]; bl[2*ng+1][1]=r[3];
            }
#pragma unroll
            for (int nt = 0; nt < 4; nt++)
#pragma unroll
                for (int mt = 0; mt < 2; mt++) {
                    MMA16816(acc[mt][nt], ah[mt], bh[nt][0], bh[nt][1]);
                    MMA16816(acc[mt][nt], ah[mt], bl[nt][0], bl[nt][1]);
                    MMA16816(acc[mt][nt], al[mt], bh[nt][0], bh[nt][1]);
                }
        }
        __syncthreads();
    }

#pragma unroll
    for (int mt = 0; mt < 2; mt++) {
#pragma unroll
        for (int half = 0; half < 2; half++) {
            const size_t slotrow =
                (size_t)(e * CAP + m0 + wm * 32 + mt * 16 + half * 8 + fr);
#pragma unroll
            for (int nt = 0; nt < 4; nt++) {
                const int gcol = n0 + wn * 32 + nt * 8 + fc;
                *(float2*)&g_Y[slotrow * DMODEL + gcol] =
                    make_float2(acc[mt][nt][half * 2 + 0],
                                acc[mt][nt][half * 2 + 1]);
            }
        }
    }
}

// ---------------- scatter back -----------------------------------------------
__global__ void scatter_kernel(const float* __restrict__ x,
                               const float* __restrict__ scores,
                               float* __restrict__ out) {
    int t = blockIdx.x;
    int i = threadIdx.x;
    int slot = g_slot_of_token[t];
    float4 v;
    if (slot < SLOTS) {
        v = *(const float4*)(g_Y + (size_t)slot * DMODEL + i * 4);
        float s = scores[t];
        v.x *= s; v.y *= s; v.z *= s; v.w *= s;
    } else {
        v = *(const float4*)(x + (size_t)t * DMODEL + i * 4);
    }
    *(float4*)(out + (size_t)t * DMODEL + i * 4) = v;
}

// -----------------------------------------------------------------------------
extern "C" void kernel_launch(void* const* d_in, const int* in_sizes, int n_in,
                              void* d_out, int out_size) {
    const float* x      = (const float*)d_in[0];
    const int*   idxw   = (const int*)d_in[1];
    const float* scores = (const float*)d_in[2];
    const float* Wg     = (const float*)d_in[3];
    const float* Wu     = (const float*)d_in[4];
    const float* Wd     = (const float*)d_in[5];
    float*       out    = (float*)d_out;

    cudaFuncSetAttribute(gemm_gu_kernel,
                         cudaFuncAttributeMaxDynamicSharedMemorySize, SMEM_GU);
    cudaFuncSetAttribute(gemm_down_kernel,
                         cudaFuncAttributeMaxDynamicSharedMemorySize, SMEM_DN);

    route_kernel<<<1, 256>>>(idxw);
    gather_kernel<<<SLOTS, 256>>>(x);

    gemm_gu_kernel<<<dim3(HDIM / BN, CAP / BM, NEXP), 256, SMEM_GU>>>(Wg, Wu);
    gemm_down_kernel<<<dim3(DMODEL / BN, CAP / BM, NEXP), 256, SMEM_DN>>>(Wd);

    scatter_kernel<<<N_TOK, 256>>>(x, scores, out);
}

// round 11
// speedup vs baseline: 1.9794x; 1.1538x over previous
#include <cuda_runtime.h>
#include <cuda_bf16.h>
#include <cstdint>

// Problem constants
#define N_TOK  8192
#define DMODEL 1024
#define NEXP   8
#define HDIM   2816
#define CAP    1280
#define SLOTS  (NEXP * CAP)          // 10240

// ---------------- device scratch (~158 MB; statics MUST stay < ~270 MB) ----
__device__ int g_slot_of_token[N_TOK];
__device__ int g_token_of_slot[SLOTS];
__device__ int g_count[NEXP];
__device__ __align__(256) __nv_bfloat16 g_xh [(size_t)SLOTS * DMODEL];
__device__ __align__(256) __nv_bfloat16 g_xl [(size_t)SLOTS * DMODEL];
__device__ __align__(256) __nv_bfloat16 g_acth[(size_t)SLOTS * HDIM];
__device__ __align__(256) __nv_bfloat16 g_actl[(size_t)SLOTS * HDIM];

__device__ __forceinline__ uint32_t smem_u32(const void* p) {
    uint32_t a;
    asm("{ .reg .u64 t; cvta.to.shared.u64 t, %1; cvt.u32.u64 %0, t; }"
        : "=r"(a) : "l"(p));
    return a;
}

#define MMA16816(d, a, b0, b1) \
    asm volatile("mma.sync.aligned.m16n8k16.row.col.f32.bf16.bf16.f32 " \
                 "{%0,%1,%2,%3}, {%4,%5,%6,%7}, {%8,%9}, {%0,%1,%2,%3};" \
                 : "+f"((d)[0]), "+f"((d)[1]), "+f"((d)[2]), "+f"((d)[3]) \
                 : "r"((a)[0]), "r"((a)[1]), "r"((a)[2]), "r"((a)[3]), \
                   "r"(b0), "r"(b1))

#define LDSM4(r, a) \
    asm volatile("ldmatrix.sync.aligned.m8n8.x4.shared.b16 {%0,%1,%2,%3}, [%4];" \
                 : "=r"((r)[0]), "=r"((r)[1]), "=r"((r)[2]), "=r"((r)[3]) : "r"(a))
#define LDSM4T(r, a) \
    asm volatile("ldmatrix.sync.aligned.m8n8.x4.trans.shared.b16 {%0,%1,%2,%3}, [%4];" \
                 : "=r"((r)[0]), "=r"((r)[1]), "=r"((r)[2]), "=r"((r)[3]) : "r"(a))

#define CP16(dst, src) \
    asm volatile("cp.async.cg.shared.global [%0], [%1], 16;" \
                 :: "r"(dst), "l"(src))
#define CP_COMMIT() asm volatile("cp.async.commit_group;" ::: "memory")
#define CP_WAIT0()  asm volatile("cp.async.wait_group 0;" ::: "memory")

// split two fp32 into packed bf16x2 hi and lo (lo = residual)
__device__ __forceinline__ void split2(float f0, float f1,
                                       uint32_t& hi, uint32_t& lo) {
    __nv_bfloat16 h0 = __float2bfloat16_rn(f0);
    __nv_bfloat16 h1 = __float2bfloat16_rn(f1);
    __nv_bfloat16 l0 = __float2bfloat16_rn(f0 - __bfloat162float(h0));
    __nv_bfloat16 l1 = __float2bfloat16_rn(f1 - __bfloat162float(h1));
    __nv_bfloat162 hp = __halves2bfloat162(h0, h1);
    __nv_bfloat162 lp = __halves2bfloat162(l0, l1);
    hi = *(uint32_t*)&hp; lo = *(uint32_t*)&lp;
}

// ---------------- routing (dtype-adaptive int32/int64) ----------------------
__global__ void route_kernel(const int* __restrict__ idxw) {
    __shared__ int s_any;
    int tid = threadIdx.x;
    if (tid == 0) s_any = 0;
    for (int s = tid; s < SLOTS; s += 256) g_token_of_slot[s] = -1;
    __syncthreads();
    int local = 0;
    for (int i = 2 * tid + 1; i < N_TOK; i += 512) local |= idxw[i];
    if (local) atomicOr(&s_any, 1);
    __syncthreads();
    const int stride = s_any ? 1 : 2;
    int warp = tid >> 5, lane = tid & 31;
    if (warp < NEXP) {
        int e = warp, cnt = 0;
        for (int base = 0; base < N_TOK; base += 32) {
            int t = base + lane;
            int ei = idxw[t * stride];
            bool m = (ei == e);
            unsigned mask = __ballot_sync(0xffffffffu, m);
            if (m) {
                int pos = cnt + __popc(mask & ((1u << lane) - 1u));
                if (pos < CAP) {
                    g_slot_of_token[t] = e * CAP + pos;
                    g_token_of_slot[e * CAP + pos] = t;
                } else {
                    g_slot_of_token[t] = SLOTS;
                }
            }
            cnt += __popc(mask);
        }
        if (lane == 0) g_count[e] = (cnt < CAP) ? cnt : CAP;
    }
}

// ---------------- gather tokens into split bf16 slot buffer ----------------
__global__ void gather_kernel(const float* __restrict__ x) {
    int s = blockIdx.x;
    int tok = g_token_of_slot[s];
    int i = threadIdx.x;              // 0..255 -> float4
    float4 v = make_float4(0.f, 0.f, 0.f, 0.f);
    if (tok >= 0) v = *(const float4*)(x + (size_t)tok * DMODEL + i * 4);
    uint32_t h01, l01, h23, l23;
    split2(v.x, v.y, h01, l01);
    split2(v.z, v.w, h23, l23);
    uint2 hv = make_uint2(h01, h23), lv = make_uint2(l01, l23);
    *(uint2*)(g_xh + (size_t)s * DMODEL + i * 4) = hv;
    *(uint2*)(g_xl + (size_t)s * DMODEL + i * 4) = lv;
}

// ---------------- prefill: out = x (passthrough for dropped tokens) --------
__global__ void prefill_kernel(const float* __restrict__ x,
                               float* __restrict__ out) {
    int t = blockIdx.x, i = threadIdx.x;
    *(float4*)(out + (size_t)t * DMODEL + i * 4) =
        *(const float4*)(x + (size_t)t * DMODEL + i * 4);
}

// ---------------- GEMM tiling ------------------------------------------------
// BM=128, BN=64, BK=32; 256 threads = 8 warps (4m x 2n), warp tile 32x32.
// A: split bf16 [BM][40], loaded via cp.async (already split in global).
// B: split bf16 K-major [BK][72], split from fp32 in the store phase.
// Double buffer, one __syncthreads per chunk.
#define BM 128
#define BN 64
#define BK 32
#define APAD 40
#define BNP 72

#define A_BUF (BM * APAD * 2)                 // 10240 bytes per buffer
#define B_BUF (BK * BNP * 2)                  // 4608 bytes per buffer
#define OFF_AL (2 * A_BUF)                    // 20480
#define OFF_B0 (4 * A_BUF)                    // 40960
#define SMEM_GU (OFF_B0 + 8 * B_BUF)          // 77824
#define SMEM_DN (OFF_B0 + 4 * B_BUF)          // 59392

// ---------------- fused gate+up GEMM ----------------------------------------
__global__ void __launch_bounds__(256, 2) gemm_gu_kernel(
        const float* __restrict__ Wg, const float* __restrict__ Wu) {
    extern __shared__ char smem[];

    const int e  = blockIdx.z;
    const int m0 = blockIdx.y * BM;
    if (m0 >= g_count[e]) return;
    const int n0 = blockIdx.x * BN;

    const size_t abase = (size_t)(e * CAP + m0) * DMODEL;
    const float* Bg = Wg + (size_t)e * DMODEL * HDIM;
    const float* Bu = Wu + (size_t)e * DMODEL * HDIM;

    const int tid  = threadIdx.x;
    const int lane = tid & 31, warp = tid >> 5;
    const int wm = warp >> 1, wn = warp & 1;
    const int fr = lane >> 2;
    const int fc = (lane & 3) * 2;

    const uint32_t sb = smem_u32(smem);
    const uint32_t aoff = (uint32_t)(wm * 32 + (lane & 15)) * (APAD * 2)
                        + (uint32_t)(lane >> 4) * 16;
    const uint32_t boff = (uint32_t)(lane & 15) * (BNP * 2)
                        + (uint32_t)(wn * 32 + (lane >> 4) * 8) * 2;

    // A: cp.async assignments (uint4 = 16B)
    const int ar0 = tid >> 2, ac0 = (tid & 3) * 8;
    const int ar1 = ar0 + 64;
    // B: float4 register prefetch
    const int br0 = tid >> 4, bc0 = (tid & 15) * 4;
    const int br1 = br0 + 16;

    auto issueA = [&](int c, int buf) {
        const int k0 = c * BK;
        const uint32_t d0 = sb + buf * A_BUF + (uint32_t)(ar0 * APAD + ac0) * 2;
        const uint32_t d1 = sb + buf * A_BUF + (uint32_t)(ar1 * APAD + ac0) * 2;
        CP16(d0,          g_xh + abase + (size_t)ar0 * DMODEL + k0 + ac0);
        CP16(d0 + OFF_AL, g_xl + abase + (size_t)ar0 * DMODEL + k0 + ac0);
        CP16(d1,          g_xh + abase + (size_t)ar1 * DMODEL + k0 + ac0);
        CP16(d1 + OFF_AL, g_xl + abase + (size_t)ar1 * DMODEL + k0 + ac0);
        CP_COMMIT();
    };

    float4 pbg0, pbg1, pbu0, pbu1;
    auto prefetchB = [&](int c) {
        const int k0 = c * BK;
        pbg0 = *(const float4*)(Bg + (size_t)(k0 + br0) * HDIM + n0 + bc0);
        pbg1 = *(const float4*)(Bg + (size_t)(k0 + br1) * HDIM + n0 + bc0);
        pbu0 = *(const float4*)(Bu + (size_t)(k0 + br0) * HDIM + n0 + bc0);
        pbu1 = *(const float4*)(Bu + (size_t)(k0 + br1) * HDIM + n0 + bc0);
    };
    auto storeB = [&](int buf) {
        __nv_bfloat16* pgh = (__nv_bfloat16*)(smem + OFF_B0 + buf * B_BUF);
        __nv_bfloat16* pgl = (__nv_bfloat16*)(smem + OFF_B0 + 2 * B_BUF + buf * B_BUF);
        __nv_bfloat16* puh = (__nv_bfloat16*)(smem + OFF_B0 + 4 * B_BUF + buf * B_BUF);
        __nv_bfloat16* pul = (__nv_bfloat16*)(smem + OFF_B0 + 6 * B_BUF + buf * B_BUF);
        uint32_t h01, l01, h23, l23;
        split2(pbg0.x, pbg0.y, h01, l01); split2(pbg0.z, pbg0.w, h23, l23);
        *(uint2*)&pgh[br0 * BNP + bc0] = make_uint2(h01, h23);
        *(uint2*)&pgl[br0 * BNP + bc0] = make_uint2(l01, l23);
        split2(pbg1.x, pbg1.y, h01, l01); split2(pbg1.z, pbg1.w, h23, l23);
        *(uint2*)&pgh[br1 * BNP + bc0] = make_uint2(h01, h23);
        *(uint2*)&pgl[br1 * BNP + bc0] = make_uint2(l01, l23);
        split2(pbu0.x, pbu0.y, h01, l01); split2(pbu0.z, pbu0.w, h23, l23);
        *(uint2*)&puh[br0 * BNP + bc0] = make_uint2(h01, h23);
        *(uint2*)&pul[br0 * BNP + bc0] = make_uint2(l01, l23);
        split2(pbu1.x, pbu1.y, h01, l01); split2(pbu1.z, pbu1.w, h23, l23);
        *(uint2*)&puh[br1 * BNP + bc0] = make_uint2(h01, h23);
        *(uint2*)&pul[br1 * BNP + bc0] = make_uint2(l01, l23);
    };

    float accG[2][4][4], accU[2][4][4];
#pragma unroll
    for (int i = 0; i < 2; i++)
#pragma unroll
        for (int j = 0; j < 4; j++)
#pragma unroll
            for (int q = 0; q < 4; q++) { accG[i][j][q] = 0.f; accU[i][j][q] = 0.f; }

    const int kchunks = DMODEL / BK;   // 32
    prefetchB(0);
    issueA(0, 0);
    storeB(0);
    prefetchB(1);
    CP_WAIT0();
    __syncthreads();

    for (int c = 0; c < kchunks; c++) {
        const int buf = c & 1;
        if (c + 1 < kchunks) {
            issueA(c + 1, buf ^ 1);
            storeB(buf ^ 1);
            if (c + 2 < kchunks) prefetchB(c + 2);
        }

        const uint32_t uAh = sb + buf * A_BUF + aoff;
        const uint32_t uAl = uAh + OFF_AL;
        const uint32_t uBg = sb + OFF_B0 + buf * B_BUF + boff;
        const uint32_t uBgl = uBg + 2 * B_BUF;
        const uint32_t uBu = uBg + 4 * B_BUF;
        const uint32_t uBul = uBg + 6 * B_BUF;

#pragma unroll
        for (int ks = 0; ks < 2; ks++) {
            uint32_t ah[2][4], al[2][4];
#pragma unroll
            for (int mt = 0; mt < 2; mt++) {
                LDSM4(ah[mt], uAh + mt * (16 * APAD * 2) + ks * 32);
                LDSM4(al[mt], uAl + mt * (16 * APAD * 2) + ks * 32);
            }
            uint32_t bgh[4][2], bgl[4][2], buh[4][2], bul[4][2];
#pragma unroll
            for (int ng = 0; ng < 2; ng++) {
                uint32_t r[4];
                const uint32_t ko = ks * (16 * BNP * 2) + ng * 32;
                LDSM4T(r, uBg + ko);
                bgh[2*ng][0]=r[0]; bgh[2*ng][1]=r[1]; bgh[2*ng+1][0]=r[2]; bgh[2*ng+1][1]=r[3];
                LDSM4T(r, uBgl + ko);
                bgl[2*ng][0]=r[0]; bgl[2*ng][1]=r[1]; bgl[2*ng+1][0]=r[2]; bgl[2*ng+1][1]=r[3];
                LDSM4T(r, uBu + ko);
                buh[2*ng][0]=r[0]; buh[2*ng][1]=r[1]; buh[2*ng+1][0]=r[2]; buh[2*ng+1][1]=r[3];
                LDSM4T(r, uBul + ko);
                bul[2*ng][0]=r[0]; bul[2*ng][1]=r[1]; bul[2*ng+1][0]=r[2]; bul[2*ng+1][1]=r[3];
            }
#pragma unroll
            for (int nt = 0; nt < 4; nt++)
#pragma unroll
                for (int mt = 0; mt < 2; mt++) {
                    MMA16816(accG[mt][nt], ah[mt], bgh[nt][0], bgh[nt][1]);
                    MMA16816(accG[mt][nt], ah[mt], bgl[nt][0], bgl[nt][1]);
                    MMA16816(accG[mt][nt], al[mt], bgh[nt][0], bgh[nt][1]);
                    MMA16816(accU[mt][nt], ah[mt], buh[nt][0], buh[nt][1]);
                    MMA16816(accU[mt][nt], ah[mt], bul[nt][0], bul[nt][1]);
                    MMA16816(accU[mt][nt], al[mt], buh[nt][0], buh[nt][1]);
                }
        }
        if (c + 1 < kchunks) CP_WAIT0();
        __syncthreads();
    }

    // ---- epilogue: act = silu(g) * u -> split bf16
#pragma unroll
    for (int mt = 0; mt < 2; mt++) {
#pragma unroll
        for (int half = 0; half < 2; half++) {
            const size_t slotrow =
                (size_t)(e * CAP + m0 + wm * 32 + mt * 16 + half * 8 + fr);
#pragma unroll
            for (int nt = 0; nt < 4; nt++) {
                const int gcol = n0 + wn * 32 + nt * 8 + fc;
                float gg0 = accG[mt][nt][half * 2 + 0];
                float gg1 = accG[mt][nt][half * 2 + 1];
                float uu0 = accU[mt][nt][half * 2 + 0];
                float uu1 = accU[mt][nt][half * 2 + 1];
                float a0 = (gg0 / (1.f + __expf(-gg0))) * uu0;
                float a1 = (gg1 / (1.f + __expf(-gg1))) * uu1;
                uint32_t hi, lo;
                split2(a0, a1, hi, lo);
                *(uint32_t*)&g_acth[slotrow * HDIM + gcol] = hi;
                *(uint32_t*)&g_actl[slotrow * HDIM + gcol] = lo;
            }
        }
    }
}

// ---------------- down GEMM + fused scatter: out[tok] = score * (ACT@Wd) ----
__global__ void __launch_bounds__(256, 2) gemm_down_kernel(
        const float* __restrict__ Wd, const float* __restrict__ scores,
        float* __restrict__ out) {
    extern __shared__ char smem[];
    __shared__ int   s_tok[BM];
    __shared__ float s_scr[BM];

    const int e  = blockIdx.z;
    const int m0 = blockIdx.y * BM;
    if (m0 >= g_count[e]) return;
    const int n0 = blockIdx.x * BN;

    const size_t abase = (size_t)(e * CAP + m0) * HDIM;
    const float* Bd = Wd + (size_t)e * HDIM * DMODEL;

    const int tid  = threadIdx.x;
    const int lane = tid & 31, warp = tid >> 5;
    const int wm = warp >> 1, wn = warp & 1;
    const int fr = lane >> 2;
    const int fc = (lane & 3) * 2;

    if (tid < BM) {
        int tok = g_token_of_slot[e * CAP + m0 + tid];
        s_tok[tid] = tok;
        s_scr[tid] = (tok >= 0) ? scores[tok] : 0.f;
    }

    const uint32_t sb = smem_u32(smem);
    const uint32_t aoff = (uint32_t)(wm * 32 + (lane & 15)) * (APAD * 2)
                        + (uint32_t)(lane >> 4) * 16;
    const uint32_t boff = (uint32_t)(lane & 15) * (BNP * 2)
                        + (uint32_t)(wn * 32 + (lane >> 4) * 8) * 2;

    const int ar0 = tid >> 2, ac0 = (tid & 3) * 8;
    const int ar1 = ar0 + 64;
    const int br0 = tid >> 4, bc0 = (tid & 15) * 4;
    const int br1 = br0 + 16;

    auto issueA = [&](int c, int buf) {
        const int k0 = c * BK;
        const uint32_t d0 = sb + buf * A_BUF + (uint32_t)(ar0 * APAD + ac0) * 2;
        const uint32_t d1 = sb + buf * A_BUF + (uint32_t)(ar1 * APAD + ac0) * 2;
        CP16(d0,          g_acth + abase + (size_t)ar0 * HDIM + k0 + ac0);
        CP16(d0 + OFF_AL, g_actl + abase + (size_t)ar0 * HDIM + k0 + ac0);
        CP16(d1,          g_acth + abase + (size_t)ar1 * HDIM + k0 + ac0);
        CP16(d1 + OFF_AL, g_actl + abase + (size_t)ar1 * HDIM + k0 + ac0);
        CP_COMMIT();
    };

    float4 pb0, pb1;
    auto prefetchB = [&](int c) {
        const int k0 = c * BK;
        pb0 = *(const float4*)(Bd + (size_t)(k0 + br0) * DMODEL + n0 + bc0);
        pb1 = *(const float4*)(Bd + (size_t)(k0 + br1) * DMODEL + n0 + bc0);
    };
    auto storeB = [&](int buf) {
        __nv_bfloat16* pBh = (__nv_bfloat16*)(smem + OFF_B0 + buf * B_BUF);
        __nv_bfloat16* pBl = (__nv_bfloat16*)(smem + OFF_B0 + 2 * B_BUF + buf * B_BUF);
        uint32_t h01, l01, h23, l23;
        split2(pb0.x, pb0.y, h01, l01); split2(pb0.z, pb0.w, h23, l23);
        *(uint2*)&pBh[br0 * BNP + bc0] = make_uint2(h01, h23);
        *(uint2*)&pBl[br0 * BNP + bc0] = make_uint2(l01, l23);
        split2(pb1.x, pb1.y, h01, l01); split2(pb1.z, pb1.w, h23, l23);
        *(uint2*)&pBh[br1 * BNP + bc0] = make_uint2(h01, h23);
        *(uint2*)&pBl[br1 * BNP + bc0] = make_uint2(l01, l23);
    };

    float acc[2][4][4];
#pragma unroll
    for (int i = 0; i < 2; i++)
#pragma unroll
        for (int j = 0; j < 4; j++)
#pragma unroll
            for (int q = 0; q < 4; q++) acc[i][j][q] = 0.f;

    const int kchunks = HDIM / BK;   // 88
    prefetchB(0);
    issueA(0, 0);
    storeB(0);
    prefetchB(1);
    CP_WAIT0();
    __syncthreads();

    for (int c = 0; c < kchunks; c++) {
        const int buf = c & 1;
        if (c + 1 < kchunks) {
            issueA(c + 1, buf ^ 1);
            storeB(buf ^ 1);
            if (c + 2 < kchunks) prefetchB(c + 2);
        }

        const uint32_t uAh = sb + buf * A_BUF + aoff;
        const uint32_t uAl = uAh + OFF_AL;
        const uint32_t uBh = sb + OFF_B0 + buf * B_BUF + boff;
        const uint32_t uBl = uBh + 2 * B_BUF;

        // ---- hoist ALL fragment loads for this chunk (both ks) ----
        uint32_t ah[2][2][4], al[2][2][4], bh[2][4][2], bl[2][4][2];
#pragma unroll
        for (int ks = 0; ks < 2; ks++) {
#pragma unroll
            for (int mt = 0; mt < 2; mt++) {
                LDSM4(ah[ks][mt], uAh + mt * (16 * APAD * 2) + ks * 32);
                LDSM4(al[ks][mt], uAl + mt * (16 * APAD * 2) + ks * 32);
            }
#pragma unroll
            for (int ng = 0; ng < 2; ng++) {
                uint32_t r[4];
                const uint32_t ko = ks * (16 * BNP * 2) + ng * 32;
                LDSM4T(r, uBh + ko);
                bh[ks][2*ng][0]=r[0]; bh[ks][2*ng][1]=r[1];
                bh[ks][2*ng+1][0]=r[2]; bh[ks][2*ng+1][1]=r[3];
                LDSM4T(r, uBl + ko);
                bl[ks][2*ng][0]=r[0]; bl[ks][2*ng][1]=r[1];
                bl[ks][2*ng+1][0]=r[2]; bl[ks][2*ng+1][1]=r[3];
            }
        }
#pragma unroll
        for (int ks = 0; ks < 2; ks++)
#pragma unroll
            for (int nt = 0; nt < 4; nt++)
#pragma unroll
                for (int mt = 0; mt < 2; mt++) {
                    MMA16816(acc[mt][nt], ah[ks][mt], bh[ks][nt][0], bh[ks][nt][1]);
                    MMA16816(acc[mt][nt], ah[ks][mt], bl[ks][nt][0], bl[ks][nt][1]);
                    MMA16816(acc[mt][nt], al[ks][mt], bh[ks][nt][0], bh[ks][nt][1]);
                }
        if (c + 1 < kchunks) CP_WAIT0();
        __syncthreads();
    }

    // ---- epilogue: out[token] = score * acc (fused scatter) ----
#pragma unroll
    for (int mt = 0; mt < 2; mt++) {
#pragma unroll
        for (int half = 0; half < 2; half++) {
            const int lrow = wm * 32 + mt * 16 + half * 8 + fr;
            const int tok = s_tok[lrow];
            if (tok < 0) continue;
            const float s = s_scr[lrow];
#pragma unroll
            for (int nt = 0; nt < 4; nt++) {
                const int gcol = n0 + wn * 32 + nt * 8 + fc;
                *(float2*)&out[(size_t)tok * DMODEL + gcol] =
                    make_float2(s * acc[mt][nt][half * 2 + 0],
                                s * acc[mt][nt][half * 2 + 1]);
            }
        }
    }
}

// -----------------------------------------------------------------------------
extern "C" void kernel_launch(void* const* d_in, const int* in_sizes, int n_in,
                              void* d_out, int out_size) {
    const float* x      = (const float*)d_in[0];
    const int*   idxw   = (const int*)d_in[1];
    const float* scores = (const float*)d_in[2];
    const float* Wg     = (const float*)d_in[3];
    const float* Wu     = (const float*)d_in[4];
    const float* Wd     = (const float*)d_in[5];
    float*       out    = (float*)d_out;

    cudaFuncSetAttribute(gemm_gu_kernel,
                         cudaFuncAttributeMaxDynamicSharedMemorySize, SMEM_GU);
    cudaFuncSetAttribute(gemm_down_kernel,
                         cudaFuncAttributeMaxDynamicSharedMemorySize, SMEM_DN);

    route_kernel<<<1, 256>>>(idxw);
    gather_kernel<<<SLOTS, 256>>>(x);
    prefill_kernel<<<N_TOK, 256>>>(x, out);

    gemm_gu_kernel<<<dim3(HDIM / BN, CAP / BM, NEXP), 256, SMEM_GU>>>(Wg, Wu);
    gemm_down_kernel<<<dim3(DMODEL / BN, CAP / BM, NEXP), 256, SMEM_DN>>>(
        Wd, scores, out);
}